// round 15
// baseline (speedup 1.0000x reference)
#include <cuda_runtime.h>
#include <cuda_bf16.h>
#include <cstdint>

// Problem dims (fixed)
constexpr int Bn = 16, Tn = 4096, In = 32, On = 32;

// Convolution formulation
constexpr int T1   = 32;            // taps, main term (tail beyond 32 < 1e-7, proven R2-R5)
constexpr int T23  = 12;            // taps, bf16-split correction terms
constexpr int LEAD = T1 - 1;        // 31 history rows
constexpr int MT   = 512;           // t-rows per CTA
constexpr int ROWS = MT + LEAD + 1; // 544 staged rows
constexpr int NCTA = Bn * (Tn / MT);// 128
constexpr int THREADS = 512;        // 16 warps, warp = 32 t-rows

// SMEM layout (bytes). Rows padded to 80B -> conflict-free ldmatrix (20r mod 32 distinct)
constexpr int AROW   = 80;
constexpr int A_HI   = 0;
constexpr int A_SZ   = ROWS * AROW;          // 43,520
constexpr int A_LO   = A_HI + A_SZ;          // 43,520
constexpr int G_HI   = A_LO + A_SZ;          // 87,040
constexpr int GTAP   = 32 * AROW;            // 2,560 per tap (32 i-rows x 80B)
constexpr int G_HISZ = T1 * GTAP;            // 81,920
constexpr int G_LO   = G_HI + G_HISZ;        // 168,960
constexpr int G_LOSZ = T23 * GTAP;           // 30,720
constexpr int SMEM_BYTES = G_LO + G_LOSZ;    // 199,680

// ---------------- device helpers ----------------
static __device__ __forceinline__ uint32_t smem_u32(const void* p) {
    uint32_t a;
    asm("{ .reg .u64 t; cvta.to.shared.u64 t, %1; cvt.u32.u64 %0, t; }" : "=r"(a) : "l"(p));
    return a;
}
static __device__ __forceinline__ void ldsm4(uint32_t& r0, uint32_t& r1, uint32_t& r2,
                                             uint32_t& r3, uint32_t addr) {
    asm volatile("ldmatrix.sync.aligned.m8n8.x4.shared.b16 {%0,%1,%2,%3}, [%4];"
                 : "=r"(r0), "=r"(r1), "=r"(r2), "=r"(r3) : "r"(addr));
}
static __device__ __forceinline__ void ldsm4t(uint32_t& r0, uint32_t& r1, uint32_t& r2,
                                              uint32_t& r3, uint32_t addr) {
    asm volatile("ldmatrix.sync.aligned.m8n8.x4.trans.shared.b16 {%0,%1,%2,%3}, [%4];"
                 : "=r"(r0), "=r"(r1), "=r"(r2), "=r"(r3) : "r"(addr));
}
static __device__ __forceinline__ void mma16816(float* d,
    uint32_t a0, uint32_t a1, uint32_t a2, uint32_t a3, uint32_t b0, uint32_t b1) {
    asm volatile(
        "mma.sync.aligned.m16n8k16.row.col.f32.bf16.bf16.f32 "
        "{%0,%1,%2,%3}, {%4,%5,%6,%7}, {%8,%9}, {%0,%1,%2,%3};"
        : "+f"(d[0]), "+f"(d[1]), "+f"(d[2]), "+f"(d[3])
        : "r"(a0), "r"(a1), "r"(a2), "r"(a3), "r"(b0), "r"(b1));
}
static __device__ __forceinline__ void split2(float f0, float f1, uint32_t& h, uint32_t& l) {
    __nv_bfloat16 a = __float2bfloat16_rn(f0), b = __float2bfloat16_rn(f1);
    h = (uint32_t)__bfloat16_as_ushort(a) | ((uint32_t)__bfloat16_as_ushort(b) << 16);
    __nv_bfloat16 la = __float2bfloat16_rn(f0 - __bfloat162float(a));
    __nv_bfloat16 lb = __float2bfloat16_rn(f1 - __bfloat162float(b));
    l = (uint32_t)__bfloat16_as_ushort(la) | ((uint32_t)__bfloat16_as_ushort(lb) << 16);
}

// One GEMM term: acc[j][nt][4] += A(shifted) x G, over `taps` taps (warp = 32 rows, j=0..1)
static __device__ __forceinline__ void gemm_term(float acc[2][4][4],
    uint32_t aBase, uint32_t bBase, int taps)
{
    #pragma unroll 1
    for (int k = 0; k < taps; ++k) {
        const uint32_t bk = bBase + k * GTAP;
        uint32_t b00,b01,b10,b11, b20,b21,b30,b31;
        uint32_t c00,c01,c10,c11, c20,c21,c30,c31;
        ldsm4t(b00, b01, b10, b11, bk);                 // kc0: nt0, nt1
        ldsm4t(b20, b21, b30, b31, bk + 32);            // kc0: nt2, nt3
        ldsm4t(c00, c01, c10, c11, bk + 16 * AROW);     // kc1: nt0, nt1
        ldsm4t(c20, c21, c30, c31, bk + 16 * AROW + 32);// kc1: nt2, nt3
        const uint32_t ak = aBase - k * AROW;
        #pragma unroll
        for (int j = 0; j < 2; ++j) {
            uint32_t a0,a1,a2,a3, e0,e1,e2,e3;
            ldsm4(a0, a1, a2, a3, ak + j * 16 * AROW);        // i 0-15
            ldsm4(e0, e1, e2, e3, ak + j * 16 * AROW + 32);   // i 16-31
            mma16816(acc[j][0], a0,a1,a2,a3, b00, b01);
            mma16816(acc[j][0], e0,e1,e2,e3, c00, c01);
            mma16816(acc[j][1], a0,a1,a2,a3, b10, b11);
            mma16816(acc[j][1], e0,e1,e2,e3, c10, c11);
            mma16816(acc[j][2], a0,a1,a2,a3, b20, b21);
            mma16816(acc[j][2], e0,e1,e2,e3, c20, c21);
            mma16816(acc[j][3], a0,a1,a2,a3, b30, b31);
            mma16816(acc[j][3], e0,e1,e2,e3, c30, c31);
        }
    }
}

// ---------------- fused kernel: per-CTA g-prep + staging + HMMA GEMM ----------------
__global__ void __launch_bounds__(THREADS, 1)
mimo_hmma2(const float* __restrict__ u_in,
           const float* __restrict__ b_co,
           const float* __restrict__ a_co,
           float* __restrict__ y_out) {
    extern __shared__ char smc[];
    const uint32_t smb = smem_u32(smc);

    const int tid  = threadIdx.x;
    const int bb   = blockIdx.x >> 3;       // batch
    const int tile = blockIdx.x & 7;        // t-tile
    const int t0   = tile * MT;

    // ---- in-CTA prep: impulse responses straight into SMEM G (2 pairs/thread) ----
    #pragma unroll
    for (int rep = 0; rep < 2; ++rep) {
        const int oi = tid + rep * THREADS;     // 0..1023 = o*32 + i
        const int o = oi >> 5, i = oi & 31;
        const float b0 = b_co[3 * oi], b1 = b_co[3 * oi + 1], b2 = b_co[3 * oi + 2];
        const float a1 = a_co[2 * oi], a2 = a_co[2 * oi + 1];
        __nv_bfloat16* ghp = (__nv_bfloat16*)(smc + G_HI + i * AROW + o * 2);
        __nv_bfloat16* glp = (__nv_bfloat16*)(smc + G_LO + i * AROW + o * 2);
        float y1 = 0.f, y2 = 0.f;
        for (int k = 0; k < T1; ++k) {
            float x = (k == 0) ? b0 : (k == 1) ? b1 : (k == 2) ? b2 : 0.f;
            float y = x - a1 * y1 - a2 * y2;
            __nv_bfloat16 h = __float2bfloat16_rn(y);
            ghp[k * (GTAP / 2)] = h;
            if (k < T23) glp[k * (GTAP / 2)] = __float2bfloat16_rn(y - __bfloat162float(h));
            y2 = y1; y1 = y;
        }
    }

    // ---- stage u tile: fp32 -> (bf16 hi, bf16 lo), 80B padded rows ----
    const float4* U4 = (const float4*)(u_in + (size_t)bb * Tn * In);
    for (int idx = tid; idx < ROWS * 8; idx += THREADS) {
        const int row = idx >> 3, q = idx & 7;
        const int t = t0 - LEAD + row;
        float4 f = make_float4(0.f, 0.f, 0.f, 0.f);
        if (t >= 0 && t < Tn) f = U4[t * 8 + q];
        uint32_t h0, h1, l0, l1;
        split2(f.x, f.y, h0, l0);
        split2(f.z, f.w, h1, l1);
        *(uint2*)(smc + A_HI + row * AROW + q * 8) = make_uint2(h0, h1);
        *(uint2*)(smc + A_LO + row * AROW + q * 8) = make_uint2(l0, l1);
    }
    __syncthreads();

    const int w    = tid >> 5;              // warp -> rows [w*32, w*32+32)
    const int lane = tid & 31;
    // per-lane ldmatrix offset: row = (lane&7) + ((lane>>3)&1)*8 ; col-half = (lane>>4)*16B
    const uint32_t laneoff = (uint32_t)(((lane & 7) + ((lane >> 3) & 1) * 8) * AROW
                                        + (lane >> 4) * 16);

    const uint32_t aHi = smb + A_HI + (uint32_t)w * 32 * AROW + LEAD * AROW + laneoff;
    const uint32_t aLo = smb + A_LO + (uint32_t)w * 32 * AROW + LEAD * AROW + laneoff;
    const uint32_t bHi = smb + G_HI + laneoff;
    const uint32_t bLo = smb + G_LO + laneoff;

    float acc[2][4][4];
    #pragma unroll
    for (int j = 0; j < 2; ++j)
        #pragma unroll
        for (int n = 0; n < 4; ++n)
            #pragma unroll
            for (int f = 0; f < 4; ++f) acc[j][n][f] = 0.f;

    gemm_term(acc, aHi, bHi, T1);    // u_hi x g_hi
    gemm_term(acc, aLo, bHi, T23);   // u_lo x g_hi
    gemm_term(acc, aHi, bLo, T23);   // u_hi x g_lo

    // ---- epilogue: D frag -> gmem (v2 stores) ----
    const int qr = lane >> 2;            // 0..7
    const int qc = (lane & 3) * 2;       // 0,2,4,6
    #pragma unroll
    for (int j = 0; j < 2; ++j) {
        const size_t rowbase = (size_t)bb * Tn + t0 + w * 32 + j * 16;
        #pragma unroll
        for (int nt = 0; nt < 4; ++nt) {
            float* p0 = y_out + (rowbase + qr) * On + nt * 8 + qc;
            *(float2*)p0 = make_float2(acc[j][nt][0], acc[j][nt][1]);
            float* p1 = p0 + 8 * On;
            *(float2*)p1 = make_float2(acc[j][nt][2], acc[j][nt][3]);
        }
    }
}

extern "C" void kernel_launch(void* const* d_in, const int* in_sizes, int n_in,
                              void* d_out, int out_size)
{
    const float* u  = (const float*)d_in[0];   // (B,T,I) f32
    const float* bc = (const float*)d_in[1];   // (O,I,3) f32
    const float* ac = (const float*)d_in[2];   // (O,I,2) f32
    float* y = (float*)d_out;                  // (B,T,O) f32

    cudaFuncSetAttribute(mimo_hmma2,
                         cudaFuncAttributeMaxDynamicSharedMemorySize, SMEM_BYTES);
    mimo_hmma2<<<NCTA, THREADS, SMEM_BYTES>>>(u, bc, ac, y);
}